// round 13
// baseline (speedup 1.0000x reference)
#include <cuda_runtime.h>

#define NLEN   8192
#define NMODES 32
#define CH     64
#define BATCH  32
#define ROWS   (BATCH * CH)        // 2048
#define RN     256                 // residues t (threads per block)
#define NB     592                 // 148 SMs x 4 blocks -> one full wave (inv only)

// scratch (allocation-free rule: __device__ globals)
__device__ float2 g_X[ROWS * NMODES];   // [row][m] (re,im), row = b*64 + i

// cos(2*pi*k/32), k = 0..31 (compile-time constants -> FFMA immediates)
// sin(2*pi*k/32) = COS32[(k+24)&31]
__device__ constexpr float COS32[32] = {
     1.0f,                  0.9807852804032304f,  0.9238795325112868f,  0.8314696123025452f,
     0.7071067811865476f,   0.5555702330196022f,  0.3826834323650898f,  0.1950903220161283f,
     0.0f,                 -0.1950903220161283f, -0.3826834323650898f, -0.5555702330196022f,
    -0.7071067811865476f,  -0.8314696123025452f, -0.9238795325112868f, -0.9807852804032304f,
    -1.0f,                 -0.9807852804032304f, -0.9238795325112868f, -0.8314696123025452f,
    -0.7071067811865476f,  -0.5555702330196022f, -0.3826834323650898f, -0.1950903220161283f,
     0.0f,                  0.1950903220161283f,  0.3826834323650898f,  0.5555702330196022f,
     0.7071067811865476f,   0.8314696123025452f,  0.9238795325112868f,  0.9807852804032304f
};

static constexpr float TWO_PI_OVER_N   = 6.283185307179586476925286766559e0f / 8192.0f;
static constexpr float TWO_PI_OVER_256 = 6.283185307179586476925286766559e0f / 256.0f;

// ---------------------------------------------------------------------------
// Kernel 1: forward truncated DFT. One block per row (2048 blocks).
// Row staged through smem with 8x LDG.128 per thread (high MLP), then the
// folded stage-1 reads conflict-free LDS.32. Rotation for modes 1..16 only;
// modes 17..31 via A[32-m] = rho^32*conj(A[m]); 4 x 16-wide butterflies.
// ---------------------------------------------------------------------------
__global__ void __launch_bounds__(RN, 4) fwd_dft_kernel(const float* __restrict__ x) {
    const int row = blockIdx.x;
    const int t   = threadIdx.x;

    __shared__ float xs[NLEN];            // 32 KB
    __shared__ float sred[8][64];

    // ---- stage row into smem: 8 coalesced LDG.128 per thread ----
    {
        const float4* xr4 = (const float4*)(x + (size_t)row * NLEN);
        float4* xs4 = (float4*)xs;
#pragma unroll
        for (int k = 0; k < 8; k++) {
            xs4[k * RN + t] = xr4[k * RN + t];
        }
    }
    __syncthreads();

    const float x0  = xs[t];
    const float x16 = xs[16 * RN + t];

    float c0 = 0.0f, c16v = 0.0f, C8 = 0.0f, S8 = 0.0f;
    float ce[7], co[7], se[7], so[7];
#pragma unroll
    for (int m = 0; m < 7; m++) { ce[m] = co[m] = se[m] = so[m] = 0.0f; }

#pragma unroll
    for (int q = 1; q <= 15; q++) {
        const float a  = xs[q * RN + t];
        const float bq = xs[(32 - q) * RN + t];
        const float e = a + bq, o = a - bq;
        c0 += e;
        c16v = (q & 1) ? (c16v - e) : (c16v + e);
        if (q & 1) { S8 = (q & 2) ? (S8 - o) : (S8 + o); }
        else       { C8 = (q & 2) ? (C8 - e) : (C8 + e); }
#pragma unroll
        for (int m = 1; m <= 7; m++) {
            const int k = (m * q) & 31;
            const float cc = COS32[k];
            const float ss = COS32[(k + 24) & 31];
            if (q & 1) { co[m - 1] = fmaf(e, cc, co[m - 1]); so[m - 1] = fmaf(o, ss, so[m - 1]); }
            else       { ce[m - 1] = fmaf(e, cc, ce[m - 1]); se[m - 1] = fmaf(o, ss, se[m - 1]); }
        }
    }

    float C[17], S[17];
    C[0] = c0;    S[0] = 0.0f;
    C[16] = c16v; S[16] = 0.0f;
    C[8] = C8;    S[8] = S8;
#pragma unroll
    for (int m = 1; m <= 7; m++) {
        C[m] = ce[m - 1] + co[m - 1];  C[16 - m] = ce[m - 1] - co[m - 1];
        S[m] = se[m - 1] + so[m - 1];  S[16 - m] = so[m - 1] - se[m - 1];
    }

    // rho = e^{-2pi i t/8192}; power ladder (exact squarings/products)
    float s1, c1;
    __sincosf(-(float)t * TWO_PI_OVER_N, &s1, &c1);
    const float c2  = c1 * c1 - s1 * s1,  s2  = 2.0f * c1 * s1;          // rho^2
    const float c4  = c2 * c2 - s2 * s2,  s4  = 2.0f * c2 * s2;          // rho^4
    const float c8p = c4 * c4 - s4 * s4,  s8p = 2.0f * c4 * s4;          // rho^8
    const float c16p = c8p * c8p - s8p * s8p, s16p = 2.0f * c8p * s8p;   // rho^16
    const float c32p = c16p * c16p - s16p * s16p, s32p = 2.0f * c16p * s16p; // rho^32
    const float c5  = c4 * c1 - s4 * s1,  s5  = c4 * s1 + s4 * c1;       // rho^5
    const float c9  = c8p * c1 - s8p * s1, s9 = c8p * s1 + s8p * c1;     // rho^9
    const float c13 = c9 * c4 - s9 * s4,  s13 = c9 * s4 + s9 * c4;       // rho^13

    const float xp = x0 + x16, xm = x0 - x16;
    const float a0re = xp + C[0];                 // mode 0: A = T (real)
    const int lane = t & 31, wid = t >> 5;
    const int comp16 = (int)(__brev((unsigned)(lane & 15)) >> 28);

#pragma unroll
    for (int g = 0; g < 4; g++) {
        float rre, rim;
        if      (g == 0) { rre = c1;  rim = s1;  }
        else if (g == 1) { rre = c5;  rim = s5;  }
        else if (g == 2) { rre = c9;  rim = s9;  }
        else             { rre = c13; rim = s13; }

        float A[16];
#pragma unroll
        for (int j = 0; j < 4; j++) {
            const int m = 4 * g + 1 + j;          // 1..16
            const float tre = ((m & 1) ? xm : xp) + C[m];
            const float tim = -S[m];
            const float Ar = tre * rre - tim * rim;
            const float Ai = tre * rim + tim * rre;
            A[2 * j]     = Ar;
            A[2 * j + 1] = Ai;
            // partner mode 32-m = rho^32 * conj(A[m]); g==3,j==3 slot -> mode 0
            if (g == 3 && j == 3) {
                A[14] = a0re;
                A[15] = 0.0f;
            } else {
                A[8 + 2 * j]     = c32p * Ar + s32p * Ai;
                A[8 + 2 * j + 1] = s32p * Ar - c32p * Ai;
            }
            const float nr = rre * c1 - rim * s1;
            const float ni = rre * s1 + rim * c1;
            rre = nr; rim = ni;
        }
        // 16-value butterfly over 32 lanes
#pragma unroll
        for (int s = 0; s < 4; s++) {
            const int half = 8 >> s;                 // 8,4,2,1
            const bool hi = (lane >> s) & 1;
#pragma unroll
            for (int i = 0; i < half; i++) {
                const float send  = hi ? A[i] : A[i + half];
                const float other = __shfl_xor_sync(0xFFFFFFFFu, send, 1 << s);
                A[i] = (hi ? A[i + half] : A[i]) + other;
            }
        }
        A[0] += __shfl_xor_sync(0xFFFFFFFFu, A[0], 16);
        if (lane < 16) sred[wid][g * 16 + comp16] = A[0];
    }
    __syncthreads();

    if (t < 64) {
        float s = 0.0f;
#pragma unroll
        for (int w = 0; w < 8; w++) s += sred[w][t];
        // component -> mode map: g = t>>4; j2 = (t&15)>>1; reim = t&1
        const int g  = t >> 4;
        const int j2 = (t & 15) >> 1;
        const int reim = t & 1;
        int M;
        if (j2 < 4)                 M = 4 * g + 1 + j2;
        else if (g == 3 && j2 == 7) M = 0;
        else                        M = 32 - (4 * g + 1 + (j2 - 4));
        ((float*)g_X)[row * 64 + 2 * M + reim] = s;
    }
}

// ---------------------------------------------------------------------------
// Kernel 2: fused channel-mix + inverse truncated DFT. 592 blocks, 3-4 rows.
// Phase A: mode-pair vectorized (X LDG.128 cached across same-b rows, W LDG.64,
// partials STS.128). One sync; reduce; one sync; phase B per row (4 rotation
// chains + 4-way folded synthesis), sync-free.
// ---------------------------------------------------------------------------
__global__ void __launch_bounds__(RN, 4) inv_mix_kernel(const float* __restrict__ wr,
                                                        const float* __restrict__ wi,
                                                        float* __restrict__ out) {
    const int t = threadIdx.x;
    const int u     = t & 15;   // mode pair: m0 = 2u, m1 = 2u+1
    const int chunk = t >> 4;   // 16 chunks x 4 channels

    const int row_start = (int)(((unsigned)blockIdx.x * ROWS) / NB);
    const int row_end   = (int)((((unsigned)blockIdx.x + 1u) * ROWS) / NB);
    const int nr = row_end - row_start;          // 3 or 4

    __shared__ float red[4][16][64];
    __shared__ float cs[4][64];

    // ---- Phase A ----
    float4 xv[4];               // X[b, i, m0..m1] (re,im,re,im) per channel
    int cur_b = -1;
#pragma unroll 1
    for (int ri = 0; ri < nr; ri++) {
        const int row = row_start + ri;
        const int b = row >> 6, o = row & 63;
        if (b != cur_b) {
#pragma unroll
            for (int j = 0; j < 4; j++) {
                xv[j] = ((const float4*)g_X)[(b * CH + chunk * 4 + j) * (NMODES / 2) + u];
            }
            cur_b = b;
        }
        float y0r = 0.0f, y0i = 0.0f, y1r = 0.0f, y1i = 0.0f;
#pragma unroll
        for (int j = 0; j < 4; j++) {
            const int i = chunk * 4 + j;
            const float2 w_r = ((const float2*)wr)[(i * CH + o) * (NMODES / 2) + u];
            const float2 w_i = ((const float2*)wi)[(i * CH + o) * (NMODES / 2) + u];
            y0r = fmaf(xv[j].x, w_r.x, y0r);
            y0r = fmaf(-xv[j].y, w_i.x, y0r);
            y0i = fmaf(xv[j].x, w_i.x, y0i);
            y0i = fmaf(xv[j].y, w_r.x, y0i);
            y1r = fmaf(xv[j].z, w_r.y, y1r);
            y1r = fmaf(-xv[j].w, w_i.y, y1r);
            y1i = fmaf(xv[j].z, w_i.y, y1i);
            y1i = fmaf(xv[j].w, w_r.y, y1i);
        }
        ((float4*)red[ri][chunk])[u] = make_float4(y0r, y0i, y1r, y1i);
    }
    __syncthreads();

    {
        const int ri = t >> 6, c = t & 63;
        if (ri < nr) {
            float s = 0.0f;
#pragma unroll
            for (int w = 0; w < 16; w++) s += red[ri][w][c];
            const int mm = c >> 1;
            const float a = (mm == 0 ? 1.0f : 2.0f) / (float)NLEN;
            cs[ri][c] = s * a;
        }
    }
    __syncthreads();

    // ---- Phase B ----
    float s1, c1, s32, c32;
    __sincosf((float)t * TWO_PI_OVER_N, &s1, &c1);     // rho = e^{+2pi i t/8192}
    __sincosf((float)t * TWO_PI_OVER_256, &s32, &c32); // rho^32
    const float c2 = c1 * c1 - s1 * s1, s2 = 2.0f * c1 * s1;
    const float c3 = c2 * c1 - s2 * s1, s3 = c2 * s1 + s2 * c1;
    const float c4 = c2 * c2 - s2 * s2, s4 = 2.0f * c2 * s2;

#pragma unroll 1
    for (int ri = 0; ri < nr; ri++) {
        const int row = row_start + ri;
        const float* csr = cs[ri];

        const float d0 = csr[0];
        float d16 = 0.0f;
        float Are[15], Bim[15];

#pragma unroll
        for (int g = 0; g < 4; g++) {
            float rre, rim;
            if      (g == 0) { rre = c1; rim = s1; }
            else if (g == 1) { rre = c2; rim = s2; }
            else if (g == 2) { rre = c3; rim = s3; }
            else             { rre = c4; rim = s4; }
            const int nsteps = (g == 3) ? 3 : 4;
#pragma unroll
            for (int jj = 0; jj < 4; jj++) {
                if (jj < nsteps) {
                    const int mq = (g + 1) + 4 * jj;
                    const float ar = csr[2 * mq],        ai = csr[2 * mq + 1];
                    const float br = csr[2 * (32 - mq)], bi = csr[2 * (32 - mq) + 1];
                    const float ur = c32 * rre + s32 * rim;  // rho32*conj(rho^m)
                    const float ui = s32 * rre - c32 * rim;
                    Are[mq - 1] = (ar * rre - ai * rim) + (br * ur - bi * ui);
                    Bim[mq - 1] = (ar * rim + ai * rre) - (br * ui + bi * ur);
                    const float nrr = rre * c4 - rim * s4;
                    const float nii = rre * s4 + rim * c4;
                    rre = nrr; rim = nii;
                }
            }
            if (g == 3) d16 = csr[32] * rre - csr[33] * rim;
        }

        float* orow = out + (size_t)row * NLEN + t;
#pragma unroll
        for (int q = 0; q <= 8; q++) {
            float Ea = 0.0f, Eb = 0.0f, Oa = 0.0f, Ob = 0.0f;
#pragma unroll
            for (int mq = 1; mq <= 15; mq++) {
                const int k = (mq * q) & 31;
                const float cc = COS32[k];
                const float ss = COS32[(k + 24) & 31];
                if (mq & 1) { Ea = fmaf(Are[mq - 1], cc, Ea); Oa = fmaf(Bim[mq - 1], ss, Oa); }
                else        { Eb = fmaf(Are[mq - 1], cc, Eb); Ob = fmaf(Bim[mq - 1], ss, Ob); }
            }
            const float base = (q & 1) ? (d0 - d16) : (d0 + d16);
            const float E1 = base + Ea + Eb;   // E(q)
            const float O1 = Oa + Ob;          // O(q)
            const float E2 = base + Eb - Ea;   // E(16-q)
            const float O2 = Oa - Ob;          // O(16-q)
            if (q == 0) {
                orow[0]       = E1;
                orow[16 * RN] = E2;
            } else if (q == 8) {
                orow[8 * RN]  = E1 - O1;
                orow[24 * RN] = E1 + O1;
            } else {
                orow[q * RN]        = E1 - O1;
                orow[(32 - q) * RN] = E1 + O1;
                orow[(16 - q) * RN] = E2 - O2;
                orow[(16 + q) * RN] = E2 + O2;
            }
        }
    }
}

// ---------------------------------------------------------------------------
extern "C" void kernel_launch(void* const* d_in, const int* in_sizes, int n_in,
                              void* d_out, int out_size) {
    const float* x  = (const float*)d_in[0];
    const float* wr = (const float*)d_in[1];
    const float* wi = (const float*)d_in[2];
    float* out = (float*)d_out;

    fwd_dft_kernel<<<ROWS, RN>>>(x);
    inv_mix_kernel<<<NB, RN>>>(wr, wi, out);
}

// round 14
// speedup vs baseline: 1.1202x; 1.1202x over previous
#include <cuda_runtime.h>

#define NLEN   8192
#define NMODES 32
#define CH     64
#define BATCH  32
#define ROWS   (BATCH * CH)        // 2048
#define RN     256                 // residues t (threads per block)
#define NB     592                 // 148 SMs x 4 blocks -> one full wave (inv only)

// scratch (allocation-free rule: __device__ globals)
__device__ float2 g_X[ROWS * NMODES];   // [row][m] (re,im), row = b*64 + i

// cos(2*pi*k/32), k = 0..31 (compile-time constants -> FFMA immediates)
// sin(2*pi*k/32) = COS32[(k+24)&31]
__device__ constexpr float COS32[32] = {
     1.0f,                  0.9807852804032304f,  0.9238795325112868f,  0.8314696123025452f,
     0.7071067811865476f,   0.5555702330196022f,  0.3826834323650898f,  0.1950903220161283f,
     0.0f,                 -0.1950903220161283f, -0.3826834323650898f, -0.5555702330196022f,
    -0.7071067811865476f,  -0.8314696123025452f, -0.9238795325112868f, -0.9807852804032304f,
    -1.0f,                 -0.9807852804032304f, -0.9238795325112868f, -0.8314696123025452f,
    -0.7071067811865476f,  -0.5555702330196022f, -0.3826834323650898f, -0.1950903220161283f,
     0.0f,                  0.1950903220161283f,  0.3826834323650898f,  0.5555702330196022f,
     0.7071067811865476f,   0.8314696123025452f,  0.9238795325112868f,  0.9807852804032304f
};

static constexpr float TWO_PI_OVER_N   = 6.283185307179586476925286766559e0f / 8192.0f;
static constexpr float TWO_PI_OVER_256 = 6.283185307179586476925286766559e0f / 256.0f;

// ---------------------------------------------------------------------------
// Kernel 1: forward truncated DFT. One block per row (2048 blocks).
// Direct loads (R10 config); stage-1 with q<->32-q, m<->16-m AND q<->16-q
// folds (~98 FMA); rotation for modes 1..16 only (conjugate trick for 17..31);
// 4 x 16-wide butterflies.
// ---------------------------------------------------------------------------
__global__ void __launch_bounds__(RN, 4) fwd_dft_kernel(const float* __restrict__ x) {
    const int row = blockIdx.x;
    const int t   = threadIdx.x;
    const float* xr = x + (size_t)row * NLEN;

    const float x0  = xr[t];
    const float x16 = xr[16 * RN + t];

    float e[15], o[15];
    float c0 = 0.0f, c16v = 0.0f, C8a = 0.0f, S8a = 0.0f;
#pragma unroll
    for (int q = 1; q <= 15; q++) {
        const float a  = xr[q * RN + t];
        const float bq = xr[(32 - q) * RN + t];
        e[q - 1] = a + bq;
        o[q - 1] = a - bq;
        c0 += e[q - 1];
        c16v = (q & 1) ? (c16v - e[q - 1]) : (c16v + e[q - 1]);
        if (q & 1) { S8a = (q & 2) ? (S8a - o[q - 1]) : (S8a + o[q - 1]); }
        else       { C8a = (q & 2) ? (C8a - e[q - 1]) : (C8a + e[q - 1]); }
    }

    // q <-> 16-q fold
    float Ue[7], Ve[7], Uo[7], Vo[7];
#pragma unroll
    for (int q = 1; q <= 7; q++) {
        Ue[q - 1] = e[q - 1] + e[15 - q];  Ve[q - 1] = e[q - 1] - e[15 - q];
        Uo[q - 1] = o[q - 1] + o[15 - q];  Vo[q - 1] = o[q - 1] - o[15 - q];
    }
    const float e8 = e[7], o8 = o[7];

    float C[17], S[17];
    C[0] = c0;    S[0] = 0.0f;
    C[16] = c16v; S[16] = 0.0f;
    C[8] = C8a;   S[8] = S8a;
#pragma unroll
    for (int m = 1; m <= 7; m++) {
        float ce = 0.0f, co = 0.0f, se = 0.0f, so = 0.0f;
#pragma unroll
        for (int q = 1; q <= 7; q++) {
            const int k = (m * q) & 31;
            const float cc = COS32[k];
            const float ss = COS32[(k + 24) & 31];
            const float fe = (m & 1) ? Ve[q - 1] : Ue[q - 1];
            const float fo = (m & 1) ? Uo[q - 1] : Vo[q - 1];
            if (q & 1) { co = fmaf(fe, cc, co); so = fmaf(fo, ss, so); }
            else       { ce = fmaf(fe, cc, ce); se = fmaf(fo, ss, se); }
        }
        // q = 8 terms (even q -> ce/se): cos(pi m/2) / sin(pi m/2)
        if (!(m & 1)) ce += ((m & 2) ? -e8 : e8);   // m=2:-1, m=4:+1, m=6:-1
        else          se += ((m & 2) ? -o8 : o8);   // m=1:+1, 3:-1, 5:+1, 7:-1
        C[m] = ce + co;  C[16 - m] = ce - co;
        S[m] = se + so;  S[16 - m] = so - se;
    }

    // rho = e^{-2pi i t/8192}; power ladder (exact squarings/products)
    float s1, c1;
    __sincosf(-(float)t * TWO_PI_OVER_N, &s1, &c1);
    const float c2  = c1 * c1 - s1 * s1,  s2  = 2.0f * c1 * s1;          // rho^2
    const float c4  = c2 * c2 - s2 * s2,  s4  = 2.0f * c2 * s2;          // rho^4
    const float c8p = c4 * c4 - s4 * s4,  s8p = 2.0f * c4 * s4;          // rho^8
    const float c16p = c8p * c8p - s8p * s8p, s16p = 2.0f * c8p * s8p;   // rho^16
    const float c32p = c16p * c16p - s16p * s16p, s32p = 2.0f * c16p * s16p; // rho^32
    const float c5  = c4 * c1 - s4 * s1,  s5  = c4 * s1 + s4 * c1;       // rho^5
    const float c9  = c8p * c1 - s8p * s1, s9 = c8p * s1 + s8p * c1;     // rho^9
    const float c13 = c9 * c4 - s9 * s4,  s13 = c9 * s4 + s9 * c4;       // rho^13

    const float xp = x0 + x16, xm = x0 - x16;
    const float a0re = xp + C[0];                 // mode 0: A = T (real)
    const int lane = t & 31, wid = t >> 5;
    const int comp16 = (int)(__brev((unsigned)(lane & 15)) >> 28);
    __shared__ float sred[8][64];

#pragma unroll
    for (int g = 0; g < 4; g++) {
        float rre, rim;
        if      (g == 0) { rre = c1;  rim = s1;  }
        else if (g == 1) { rre = c5;  rim = s5;  }
        else if (g == 2) { rre = c9;  rim = s9;  }
        else             { rre = c13; rim = s13; }

        float A[16];
#pragma unroll
        for (int j = 0; j < 4; j++) {
            const int m = 4 * g + 1 + j;          // 1..16
            const float tre = ((m & 1) ? xm : xp) + C[m];
            const float tim = -S[m];
            const float Ar = tre * rre - tim * rim;
            const float Ai = tre * rim + tim * rre;
            A[2 * j]     = Ar;
            A[2 * j + 1] = Ai;
            // partner mode 32-m = rho^32 * conj(A[m]); g==3,j==3 slot -> mode 0
            if (g == 3 && j == 3) {
                A[14] = a0re;
                A[15] = 0.0f;
            } else {
                A[8 + 2 * j]     = c32p * Ar + s32p * Ai;
                A[8 + 2 * j + 1] = s32p * Ar - c32p * Ai;
            }
            const float nr = rre * c1 - rim * s1;
            const float ni = rre * s1 + rim * c1;
            rre = nr; rim = ni;
        }
        // 16-value butterfly over 32 lanes
#pragma unroll
        for (int s = 0; s < 4; s++) {
            const int half = 8 >> s;                 // 8,4,2,1
            const bool hi = (lane >> s) & 1;
#pragma unroll
            for (int i = 0; i < half; i++) {
                const float send  = hi ? A[i] : A[i + half];
                const float other = __shfl_xor_sync(0xFFFFFFFFu, send, 1 << s);
                A[i] = (hi ? A[i + half] : A[i]) + other;
            }
        }
        A[0] += __shfl_xor_sync(0xFFFFFFFFu, A[0], 16);
        if (lane < 16) sred[wid][g * 16 + comp16] = A[0];
    }
    __syncthreads();

    if (t < 64) {
        float s = 0.0f;
#pragma unroll
        for (int w = 0; w < 8; w++) s += sred[w][t];
        // component -> mode map: g = t>>4; j2 = (t&15)>>1; reim = t&1
        const int g  = t >> 4;
        const int j2 = (t & 15) >> 1;
        const int reim = t & 1;
        int M;
        if (j2 < 4)                 M = 4 * g + 1 + j2;
        else if (g == 3 && j2 == 7) M = 0;
        else                        M = 32 - (4 * g + 1 + (j2 - 4));
        ((float*)g_X)[row * 64 + 2 * M + reim] = s;
    }
}

// ---------------------------------------------------------------------------
// Kernel 2: fused channel-mix + inverse truncated DFT. 592 blocks, 3-4 rows.
// Phase A vectorized; phase B: 4 rotation chains produce Are/Bim, then
// m<->16-m folded synthesis (m=1..7 per q, compile-time parity selects) with
// the existing 4-way output fold (q, 16-q, 16+q, 32-q).
// ---------------------------------------------------------------------------
__global__ void __launch_bounds__(RN, 4) inv_mix_kernel(const float* __restrict__ wr,
                                                        const float* __restrict__ wi,
                                                        float* __restrict__ out) {
    const int t = threadIdx.x;
    const int u     = t & 15;   // mode pair: m0 = 2u, m1 = 2u+1
    const int chunk = t >> 4;   // 16 chunks x 4 channels

    const int row_start = (int)(((unsigned)blockIdx.x * ROWS) / NB);
    const int row_end   = (int)((((unsigned)blockIdx.x + 1u) * ROWS) / NB);
    const int nr = row_end - row_start;          // 3 or 4

    __shared__ float red[4][16][64];
    __shared__ float cs[4][64];

    // ---- Phase A ----
    float4 xv[4];               // X[b, i, m0..m1] (re,im,re,im) per channel
    int cur_b = -1;
#pragma unroll 1
    for (int ri = 0; ri < nr; ri++) {
        const int row = row_start + ri;
        const int b = row >> 6, oo = row & 63;
        if (b != cur_b) {
#pragma unroll
            for (int j = 0; j < 4; j++) {
                xv[j] = ((const float4*)g_X)[(b * CH + chunk * 4 + j) * (NMODES / 2) + u];
            }
            cur_b = b;
        }
        float y0r = 0.0f, y0i = 0.0f, y1r = 0.0f, y1i = 0.0f;
#pragma unroll
        for (int j = 0; j < 4; j++) {
            const int i = chunk * 4 + j;
            const float2 w_r = ((const float2*)wr)[(i * CH + oo) * (NMODES / 2) + u];
            const float2 w_i = ((const float2*)wi)[(i * CH + oo) * (NMODES / 2) + u];
            y0r = fmaf(xv[j].x, w_r.x, y0r);
            y0r = fmaf(-xv[j].y, w_i.x, y0r);
            y0i = fmaf(xv[j].x, w_i.x, y0i);
            y0i = fmaf(xv[j].y, w_r.x, y0i);
            y1r = fmaf(xv[j].z, w_r.y, y1r);
            y1r = fmaf(-xv[j].w, w_i.y, y1r);
            y1i = fmaf(xv[j].z, w_i.y, y1i);
            y1i = fmaf(xv[j].w, w_r.y, y1i);
        }
        ((float4*)red[ri][chunk])[u] = make_float4(y0r, y0i, y1r, y1i);
    }
    __syncthreads();

    {
        const int ri = t >> 6, c = t & 63;
        if (ri < nr) {
            float s = 0.0f;
#pragma unroll
            for (int w = 0; w < 16; w++) s += red[ri][w][c];
            const int mm = c >> 1;
            const float a = (mm == 0 ? 1.0f : 2.0f) / (float)NLEN;
            cs[ri][c] = s * a;
        }
    }
    __syncthreads();

    // ---- Phase B ----
    float s1, c1, s32, c32;
    __sincosf((float)t * TWO_PI_OVER_N, &s1, &c1);     // rho = e^{+2pi i t/8192}
    __sincosf((float)t * TWO_PI_OVER_256, &s32, &c32); // rho^32
    const float c2 = c1 * c1 - s1 * s1, s2 = 2.0f * c1 * s1;
    const float c3 = c2 * c1 - s2 * s1, s3 = c2 * s1 + s2 * c1;
    const float c4 = c2 * c2 - s2 * s2, s4 = 2.0f * c2 * s2;

#pragma unroll 1
    for (int ri = 0; ri < nr; ri++) {
        const int row = row_start + ri;
        const float* csr = cs[ri];

        const float d0 = csr[0];
        float d16 = 0.0f;
        float Are[15], Bim[15];

#pragma unroll
        for (int g = 0; g < 4; g++) {
            float rre, rim;
            if      (g == 0) { rre = c1; rim = s1; }
            else if (g == 1) { rre = c2; rim = s2; }
            else if (g == 2) { rre = c3; rim = s3; }
            else             { rre = c4; rim = s4; }
            const int nsteps = (g == 3) ? 3 : 4;
#pragma unroll
            for (int jj = 0; jj < 4; jj++) {
                if (jj < nsteps) {
                    const int mq = (g + 1) + 4 * jj;
                    const float ar = csr[2 * mq],        ai = csr[2 * mq + 1];
                    const float br = csr[2 * (32 - mq)], bi = csr[2 * (32 - mq) + 1];
                    const float ur = c32 * rre + s32 * rim;  // rho32*conj(rho^m)
                    const float ui = s32 * rre - c32 * rim;
                    Are[mq - 1] = (ar * rre - ai * rim) + (br * ur - bi * ui);
                    Bim[mq - 1] = (ar * rim + ai * rre) - (br * ui + bi * ur);
                    const float nrr = rre * c4 - rim * s4;
                    const float nii = rre * s4 + rim * c4;
                    rre = nrr; rim = nii;
                }
            }
            if (g == 3) d16 = csr[32] * rre - csr[33] * rim;
        }

        // m <-> 16-m fold
        float Pe[7], Me[7], PB[7], MB[7];
#pragma unroll
        for (int m = 1; m <= 7; m++) {
            Pe[m - 1] = Are[m - 1] + Are[15 - m];
            Me[m - 1] = Are[m - 1] - Are[15 - m];
            PB[m - 1] = Bim[m - 1] - Bim[15 - m];
            MB[m - 1] = Bim[m - 1] + Bim[15 - m];
        }
        const float A8 = Are[7], B8 = Bim[7];

        float* orow = out + (size_t)row * NLEN + t;
#pragma unroll
        for (int q = 0; q <= 8; q++) {
            float Ea = 0.0f, Eb = 0.0f, Oa = 0.0f, Ob = 0.0f;
#pragma unroll
            for (int m = 1; m <= 7; m++) {
                const int k = (m * q) & 31;
                const float cc = COS32[k];
                const float ss = COS32[(k + 24) & 31];
                const float fa = (q & 1) ? Me[m - 1] : Pe[m - 1];
                const float fb = (q & 1) ? MB[m - 1] : PB[m - 1];
                if (m & 1) { Ea = fmaf(fa, cc, Ea); Oa = fmaf(fb, ss, Oa); }
                else       { Eb = fmaf(fa, cc, Eb); Ob = fmaf(fb, ss, Ob); }
            }
            // m = 8 terms: cos(pi q/2), sin(pi q/2) -> compile-time signs
            const float t8c = ((q & 3) == 0) ? A8 : (((q & 3) == 2) ? -A8 : 0.0f);
            const float t8s = ((q & 3) == 1) ? B8 : (((q & 3) == 3) ? -B8 : 0.0f);
            const float base = (q & 1) ? (d0 - d16) : (d0 + d16);
            const float E1 = base + Ea + Eb + t8c;   // E(q)
            const float O1 = Oa + Ob + t8s;          // O(q)
            const float E2 = base + Eb - Ea + t8c;   // E(16-q)
            const float O2 = Oa - Ob - t8s;          // O(16-q)
            if (q == 0) {
                orow[0]       = E1;
                orow[16 * RN] = E2;
            } else if (q == 8) {
                orow[8 * RN]  = E1 - O1;
                orow[24 * RN] = E1 + O1;
            } else {
                orow[q * RN]        = E1 - O1;
                orow[(32 - q) * RN] = E1 + O1;
                orow[(16 - q) * RN] = E2 - O2;
                orow[(16 + q) * RN] = E2 + O2;
            }
        }
    }
}

// ---------------------------------------------------------------------------
extern "C" void kernel_launch(void* const* d_in, const int* in_sizes, int n_in,
                              void* d_out, int out_size) {
    const float* x  = (const float*)d_in[0];
    const float* wr = (const float*)d_in[1];
    const float* wi = (const float*)d_in[2];
    float* out = (float*)d_out;

    fwd_dft_kernel<<<ROWS, RN>>>(x);
    inv_mix_kernel<<<NB, RN>>>(wr, wi, out);
}